// round 3
// baseline (speedup 1.0000x reference)
#include <cuda_runtime.h>
#include <cuda_bf16.h>

// out[0,d,h,w,c] = in[0, z[d], row[h], col[w], 0]
// in (1,128,128,128,32) f32; z/row/col (64,) i32; out (1,64,64,64,32) f32.
//
// Block = 256 threads = 256 spatial positions.
// Phase 1: each thread does one independent gather -> smem (256 loads in flight).
// Phase 2: coalesced broadcast stores, 32KB per block.

__global__ __launch_bounds__(256) void sdown3d_kernel(
    const float* __restrict__ in,
    const int* __restrict__ zi,
    const int* __restrict__ ri,
    const int* __restrict__ ci,
    float4* __restrict__ out)
{
    __shared__ float sval[256];

    int t = threadIdx.x;
    int pos = blockIdx.x * 256 + t;          // spatial position 0..64^3-1
    int w = pos & 63;
    int h = (pos >> 6) & 63;
    int d = pos >> 12;

    // gather: fully independent per thread
    int src = (__ldg(zi + d) << 7) + __ldg(ri + h);     // z*128 + row
    src = ((src << 7) + __ldg(ci + w)) << 5;            // (*128 + col)*32
    sval[t] = __ldg(in + src);

    __syncthreads();

    // broadcast-write: 8 x 256 consecutive float4s per block (32KB), fully coalesced
    float4* obase = out + (long long)blockIdx.x * 2048;
    #pragma unroll
    for (int j = 0; j < 8; j++) {
        float v = sval[j * 32 + (t >> 3)];
        obase[j * 256 + t] = make_float4(v, v, v, v);
    }
}

extern "C" void kernel_launch(void* const* d_in, const int* in_sizes, int n_in,
                              void* d_out, int out_size)
{
    const float* in  = (const float*)d_in[0];
    const int*   zi  = (const int*)d_in[1];
    const int*   ri  = (const int*)d_in[2];
    const int*   ci  = (const int*)d_in[3];
    float4*      out = (float4*)d_out;

    // 64^3 positions / 256 per block = 1024 blocks
    sdown3d_kernel<<<1024, 256>>>(in, zi, ri, ci, out);
}

// round 4
// speedup vs baseline: 1.0087x; 1.0087x over previous
#include <cuda_runtime.h>
#include <cuda_bf16.h>

// out[0,d,h,w,c] = in[0, z[d], row[h], col[w], 0]
// in (1,128,128,128,32) f32; z/row/col (64,) i32; out (1,64,64,64,32) f32.
//
// Warp-centric: each lane gathers one position's scalar (32 independent LDGs/warp),
// then 8 SHFL+STG.128 rounds write 32 positions x 128B, fully coalesced.
// No smem, no __syncthreads. 2 groups per warp, unrolled, for gather MLP=64.

__global__ __launch_bounds__(256) void sdown3d_kernel(
    const float* __restrict__ in,
    const int* __restrict__ zi,
    const int* __restrict__ ri,
    const int* __restrict__ ci,
    float4* __restrict__ out)
{
    const int lane = threadIdx.x & 31;
    const int warp = threadIdx.x >> 5;
    // block handles 512 positions: 8 warps x 2 groups x 32 positions
    const int blockBase = blockIdx.x * 512;

    #pragma unroll
    for (int g = 0; g < 2; g++) {
        int pos = blockBase + (warp * 2 + g) * 32 + lane;
        int wq = pos & 63;
        int h  = (pos >> 6) & 63;
        int d  = pos >> 12;

        int src = (__ldg(zi + d) << 7) + __ldg(ri + h);   // z*128 + row
        src = ((src << 7) + __ldg(ci + wq)) << 5;         // (*128 + col)*32
        float v = __ldg(in + src);

        // 32 positions -> 256 consecutive float4s (4KB), 8 warp-wide stores
        float4* ob = out + (size_t)(pos - lane) * 8;
        #pragma unroll
        for (int i = 0; i < 8; i++) {
            float s = __shfl_sync(0xffffffffu, v, i * 4 + (lane >> 3));
            __stcs(&ob[i * 32 + lane], make_float4(s, s, s, s));
        }
    }
}

extern "C" void kernel_launch(void* const* d_in, const int* in_sizes, int n_in,
                              void* d_out, int out_size)
{
    const float* in  = (const float*)d_in[0];
    const int*   zi  = (const int*)d_in[1];
    const int*   ri  = (const int*)d_in[2];
    const int*   ci  = (const int*)d_in[3];
    float4*      out = (float4*)d_out;

    // 64^3 = 262144 positions / 512 per block = 512 blocks
    sdown3d_kernel<<<512, 256>>>(in, zi, ri, ci, out);
}